// round 2
// baseline (speedup 1.0000x reference)
#include <cuda_runtime.h>
#include <math.h>

#define NN 100000
#define EE 1600000
#define HH 128
#define GG 64
#define LL 2
#define TR 64           // MLP rows per block
#define INV_STD 0.9999950000374997f

// ---------------- scratch (device globals; no allocation) ----------------
__device__ float g_h[NN * HH];        // node features
__device__ float g_z[NN * HH];        // pre-MLP features
__device__ int   g_src[EE];
__device__ int   g_dst[EE];
__device__ int   g_eid[EE];           // edge ids sorted by dst (CSR)
__device__ int   g_deg[NN];
__device__ int   g_off[NN + 1];
__device__ int   g_fill[NN];
__device__ int   g_batch[NN];
__device__ float g_pooled[GG * HH];
__device__ float g_cnt[GG];
__device__ float g_hc[GG * 64];
__device__ int   g_flag[2];           // [0]: edge_index is int64, [1]: batch is int64

// ---------------- zero kernels ----------------
__global__ void k_zero1() {
    int i = blockIdx.x * blockDim.x + threadIdx.x;
    if (i < NN) { g_deg[i] = 0; g_fill[i] = 0; }
}
__global__ void k_zero2() {
    int i = blockIdx.x * blockDim.x + threadIdx.x;
    if (i < GG * HH) g_pooled[i] = 0.0f;
    if (i < GG) g_cnt[i] = 0.0f;
}

// ---------------- dtype probe ----------------
// If the int64 interpretation of sampled elements stays in-range, data is
// really int64; int32 data read as int64 packs two indices per ll and the
// high word is almost surely nonzero for random indices in [0, N).
__global__ void k_detect(const void* ei, const void* bt) {
    int lane = threadIdx.x;
    bool bad = false;
    const long long* p = (const long long*)ei;
    for (int k = lane; k < 512; k += 32) {
        long long v = p[(long long)k * 3125];      // spread over first EE lls
        if (v < 0 || v >= NN) bad = true;
    }
    unsigned m = __ballot_sync(0xffffffffu, bad);
    if (lane == 0) g_flag[0] = (m == 0) ? 1 : 0;

    bad = false;
    const long long* q = (const long long*)bt;
    for (int k = lane; k < 512; k += 32) {
        long long v = q[(long long)k * 97];        // spread over first NN/2 lls
        if (v < 0 || v >= GG) bad = true;
    }
    m = __ballot_sync(0xffffffffu, bad);
    if (lane == 0) g_flag[1] = (m == 0) ? 1 : 0;
}

// ---------------- index normalization + degree count ----------------
__global__ void k_cvt_edges(const void* ei) {
    int e = blockIdx.x * blockDim.x + threadIdx.x;
    if (e >= EE) return;
    int s, d;
    if (g_flag[0]) {
        const long long* p = (const long long*)ei;
        s = (int)p[e]; d = (int)p[EE + e];
    } else {
        const int* p = (const int*)ei;
        s = p[e]; d = p[EE + e];
    }
    g_src[e] = s; g_dst[e] = d;
    atomicAdd(&g_deg[d], 1);
}
__global__ void k_cvt_batch(const void* bt) {
    int i = blockIdx.x * blockDim.x + threadIdx.x;
    if (i >= NN) return;
    if (g_flag[1]) g_batch[i] = (int)((const long long*)bt)[i];
    else           g_batch[i] = ((const int*)bt)[i];
}

// ---------------- node encoder: h = x @ enc_w + enc_b ----------------
__global__ void k_encode(const float* __restrict__ x,
                         const float* __restrict__ ew,
                         const float* __restrict__ eb) {
    int idx = blockIdx.x * blockDim.x + threadIdx.x;   // over NN*32 float4s
    if (idx >= NN * 32) return;
    int i = idx >> 5, q = idx & 31;
    float xv = __ldg(&x[i]);
    float4 w = ((const float4*)ew)[q];
    float4 b = ((const float4*)eb)[q];
    float4 o;
    o.x = fmaf(xv, w.x, b.x); o.y = fmaf(xv, w.y, b.y);
    o.z = fmaf(xv, w.z, b.z); o.w = fmaf(xv, w.w, b.w);
    ((float4*)g_h)[idx] = o;
}

// ---------------- single-block exclusive scan of degrees ----------------
__global__ void k_scan() {
    const int C = (NN + 1023) / 1024;   // 98
    __shared__ int sm[1024];
    int t = threadIdx.x;
    int b0 = t * C, b1 = min(b0 + C, NN);
    int loc = 0;
    for (int i = b0; i < b1; i++) loc += g_deg[i];
    sm[t] = loc;
    __syncthreads();
    for (int d = 1; d < 1024; d <<= 1) {
        int v = 0;
        if (t >= d) v = sm[t - d];
        __syncthreads();
        sm[t] += v;
        __syncthreads();
    }
    int run = sm[t] - loc;   // exclusive prefix
    for (int i = b0; i < b1; i++) { g_off[i] = run; run += g_deg[i]; }
    if (t == 1023) g_off[NN] = sm[1023];
}

__global__ void k_fill() {
    int e = blockIdx.x * blockDim.x + threadIdx.x;
    if (e >= EE) return;
    int d = g_dst[e];
    int slot = atomicAdd(&g_fill[d], 1);
    g_eid[g_off[d] + slot] = e;
}

// ---------------- GINE aggregation: z = (1+eps)*h + sum relu(h[src]+ea) ----
__global__ void k_agg(const float* __restrict__ eattr,
                      const float* __restrict__ ew,
                      const float* __restrict__ eb,
                      const float* __restrict__ eps, int l) {
    int warp = (blockIdx.x * blockDim.x + threadIdx.x) >> 5;
    int lane = threadIdx.x & 31;
    if (warp >= NN) return;
    float epsv = 1.0f + __ldg(&eps[l]);
    float4 ew4 = ((const float4*)ew)[lane];
    float4 eb4 = ((const float4*)eb)[lane];
    const float4* hf = (const float4*)g_h;
    float4 acc = hf[warp * 32 + lane];
    acc.x *= epsv; acc.y *= epsv; acc.z *= epsv; acc.w *= epsv;
    int i0 = g_off[warp], i1 = g_off[warp + 1];
    for (int i = i0; i < i1; i++) {
        int e = __ldg(&g_eid[i]);
        int s = __ldg(&g_src[e]);
        float a = __ldg(&eattr[e]);
        float4 hv = hf[s * 32 + lane];
        float m;
        m = fmaf(a, ew4.x, eb4.x) + hv.x; acc.x += fmaxf(m, 0.0f);
        m = fmaf(a, ew4.y, eb4.y) + hv.y; acc.y += fmaxf(m, 0.0f);
        m = fmaf(a, ew4.z, eb4.z) + hv.z; acc.z += fmaxf(m, 0.0f);
        m = fmaf(a, ew4.w, eb4.w) + hv.w; acc.w += fmaxf(m, 0.0f);
    }
    ((float4*)g_z)[warp * 32 + lane] = acc;
}

// ---------------- fused MLP + BN(eval) + ReLU ----------------
// h = relu(gamma * (relu(z@w1+b1)@w2 + b2) * inv_std + beta)
__global__ __launch_bounds__(256, 1)
void k_mlp(const float* __restrict__ w1, const float* __restrict__ b1,
           const float* __restrict__ w2, const float* __restrict__ b2,
           const float* __restrict__ gam, const float* __restrict__ bet) {
    extern __shared__ float sm[];
    float4* sw1 = (float4*)sm;             // 4096 float4
    float4* sw2 = (float4*)(sm + 16384);   // 4096 float4
    float4* st  = (float4*)(sm + 32768);   // TR*32 float4
    int tid = threadIdx.x;

    const float4* w1f = (const float4*)w1;
    const float4* w2f = (const float4*)w2;
    for (int i = tid; i < 4096; i += 256) { sw1[i] = w1f[i]; sw2[i] = w2f[i]; }

    int r0 = blockIdx.x * TR;
    const float4* zf = (const float4*)g_z;
    for (int i = tid; i < TR * 32; i += 256) {
        int r = r0 + (i >> 5);
        st[i] = (r < NN) ? zf[r * 32 + (i & 31)] : make_float4(0.f, 0.f, 0.f, 0.f);
    }
    __syncthreads();

    int c4 = tid & 31;          // owns cols 4*c4 .. 4*c4+3
    int rg = tid >> 5;          // row group; same for all lanes of a warp
    float4 acc[8];
#pragma unroll
    for (int j = 0; j < 8; j++) acc[j] = make_float4(0.f, 0.f, 0.f, 0.f);

    // ---- matmul 1: u = z @ w1 ----
    for (int k = 0; k < 128; k += 4) {
        float4 wa = sw1[(k + 0) * 32 + c4];
        float4 wb = sw1[(k + 1) * 32 + c4];
        float4 wc = sw1[(k + 2) * 32 + c4];
        float4 wd = sw1[(k + 3) * 32 + c4];
#pragma unroll
        for (int j = 0; j < 8; j++) {
            float4 zv = st[(rg + 8 * j) * 32 + (k >> 2)];
            acc[j].x += zv.x * wa.x + zv.y * wb.x + zv.z * wc.x + zv.w * wd.x;
            acc[j].y += zv.x * wa.y + zv.y * wb.y + zv.z * wc.y + zv.w * wd.y;
            acc[j].z += zv.x * wa.z + zv.y * wb.z + zv.z * wc.z + zv.w * wd.z;
            acc[j].w += zv.x * wa.w + zv.y * wb.w + zv.z * wc.w + zv.w * wd.w;
        }
    }
    float4 b1v = ((const float4*)b1)[c4];
    __syncthreads();           // everyone done reading z tile
#pragma unroll
    for (int j = 0; j < 8; j++) {
        float4 u;
        u.x = fmaxf(acc[j].x + b1v.x, 0.0f);
        u.y = fmaxf(acc[j].y + b1v.y, 0.0f);
        u.z = fmaxf(acc[j].z + b1v.z, 0.0f);
        u.w = fmaxf(acc[j].w + b1v.w, 0.0f);
        st[(rg + 8 * j) * 32 + c4] = u;
        acc[j] = make_float4(0.f, 0.f, 0.f, 0.f);
    }
    __syncthreads();

    // ---- matmul 2: y = u @ w2 ----
    for (int k = 0; k < 128; k += 4) {
        float4 wa = sw2[(k + 0) * 32 + c4];
        float4 wb = sw2[(k + 1) * 32 + c4];
        float4 wc = sw2[(k + 2) * 32 + c4];
        float4 wd = sw2[(k + 3) * 32 + c4];
#pragma unroll
        for (int j = 0; j < 8; j++) {
            float4 uv = st[(rg + 8 * j) * 32 + (k >> 2)];
            acc[j].x += uv.x * wa.x + uv.y * wb.x + uv.z * wc.x + uv.w * wd.x;
            acc[j].y += uv.x * wa.y + uv.y * wb.y + uv.z * wc.y + uv.w * wd.y;
            acc[j].z += uv.x * wa.z + uv.y * wb.z + uv.z * wc.z + uv.w * wd.z;
            acc[j].w += uv.x * wa.w + uv.y * wb.w + uv.z * wc.w + uv.w * wd.w;
        }
    }
    float4 b2v = ((const float4*)b2)[c4];
    float4 gv  = ((const float4*)gam)[c4];
    float4 bv  = ((const float4*)bet)[c4];
#pragma unroll
    for (int j = 0; j < 8; j++) {
        int gr = r0 + rg + 8 * j;
        if (gr < NN) {
            float4 o;
            o.x = fmaxf(gv.x * (acc[j].x + b2v.x) * INV_STD + bv.x, 0.0f);
            o.y = fmaxf(gv.y * (acc[j].y + b2v.y) * INV_STD + bv.y, 0.0f);
            o.z = fmaxf(gv.z * (acc[j].z + b2v.z) * INV_STD + bv.z, 0.0f);
            o.w = fmaxf(gv.w * (acc[j].w + b2v.w) * INV_STD + bv.w, 0.0f);
            ((float4*)g_h)[gr * 32 + c4] = o;
        }
    }
}

// ---------------- mean pool (batch is sorted: accumulate + flush) --------
__global__ void k_pool() {
    int c = threadIdx.x;                 // 128 threads = 128 cols
    int i0 = blockIdx.x * 1024;
    int i1 = min(i0 + 1024, NN);
    if (i0 >= NN) return;
    int gcur = g_batch[i0];
    float acc = 0.0f, cacc = 0.0f;
    for (int i = i0; i < i1; i++) {
        int b = g_batch[i];
        if (b != gcur) {
            atomicAdd(&g_pooled[gcur * HH + c], acc);
            if (c == 0) atomicAdd(&g_cnt[gcur], cacc);
            acc = 0.0f; cacc = 0.0f; gcur = b;
        }
        acc += g_h[i * HH + c];
        cacc += 1.0f;
    }
    atomicAdd(&g_pooled[gcur * HH + c], acc);
    if (c == 0) atomicAdd(&g_cnt[gcur], cacc);
}

// ---------------- classifier ----------------
__global__ void k_cls1(const float* __restrict__ cw1, const float* __restrict__ cb1) {
    int idx = blockIdx.x * blockDim.x + threadIdx.x;   // 4096 = 64 graphs * 64 hid
    if (idx >= GG * 64) return;
    int g = idx >> 6, j = idx & 63;
    float s = 0.0f;
    for (int c = 0; c < HH; c++)
        s = fmaf(g_pooled[g * HH + c], __ldg(&cw1[c * 64 + j]), s);
    float cn = fmaxf(g_cnt[g], 1.0f);
    g_hc[idx] = fmaxf(s / cn + __ldg(&cb1[j]), 0.0f);
}
__global__ void k_cls2(const float* __restrict__ cw2, const float* __restrict__ cb2,
                       float* __restrict__ out) {
    int g = threadIdx.x;
    if (g >= GG) return;
    float s = __ldg(&cb2[0]);
    for (int j = 0; j < 64; j++)
        s = fmaf(g_hc[g * 64 + j], __ldg(&cw2[j]), s);
    out[g] = 1.0f / (1.0f + expf(-s));
}

// ---------------- launch ----------------
extern "C" void kernel_launch(void* const* d_in, const int* in_sizes, int n_in,
                              void* d_out, int out_size) {
    const float* x      = (const float*)d_in[0];
    const void*  ei     = d_in[1];
    const float* eattr  = (const float*)d_in[2];
    const void*  bt     = d_in[3];
    const float* enc_w  = (const float*)d_in[4];
    const float* enc_b  = (const float*)d_in[5];
    const float* eenc_w = (const float*)d_in[6];
    const float* eenc_b = (const float*)d_in[7];
    const float* eps    = (const float*)d_in[8];
    const float* w1     = (const float*)d_in[9];
    const float* b1     = (const float*)d_in[10];
    const float* w2     = (const float*)d_in[11];
    const float* b2     = (const float*)d_in[12];
    const float* gamma  = (const float*)d_in[13];
    const float* beta   = (const float*)d_in[14];
    const float* cw1    = (const float*)d_in[15];
    const float* cb1    = (const float*)d_in[16];
    const float* cw2    = (const float*)d_in[17];
    const float* cb2    = (const float*)d_in[18];
    float* out = (float*)d_out;

    cudaFuncSetAttribute(k_mlp, cudaFuncAttributeMaxDynamicSharedMemorySize, 163840);

    k_zero1<<<(NN + 255) / 256, 256>>>();
    k_zero2<<<(GG * HH + 255) / 256, 256>>>();
    k_detect<<<1, 32>>>(ei, bt);
    k_cvt_edges<<<(EE + 255) / 256, 256>>>(ei);
    k_cvt_batch<<<(NN + 255) / 256, 256>>>(bt);
    k_encode<<<(NN * 32 + 255) / 256, 256>>>(x, enc_w, enc_b);
    k_scan<<<1, 1024>>>();
    k_fill<<<(EE + 255) / 256, 256>>>();

    for (int l = 0; l < LL; l++) {
        k_agg<<<(NN + 7) / 8, 256>>>(eattr, eenc_w, eenc_b, eps, l);
        k_mlp<<<(NN + TR - 1) / TR, 256, 163840>>>(
            w1 + l * HH * HH, b1 + l * HH,
            w2 + l * HH * HH, b2 + l * HH,
            gamma + l * HH, beta + l * HH);
    }

    k_pool<<<(NN + 1023) / 1024, 128>>>();
    k_cls1<<<(GG * 64 + 255) / 256, 256>>>(cw1, cb1);
    k_cls2<<<1, 64>>>(cw2, cb2, out);
}

// round 3
// speedup vs baseline: 1.1296x; 1.1296x over previous
#include <cuda_runtime.h>
#include <math.h>

#define NN 100000
#define EE 1600000
#define HH 128
#define GG 64
#define LL 2
#define TR 128          // MLP rows per block
#define INV_STD 0.9999950000374997f

// ---------------- scratch (device globals; no allocation) ----------------
__device__ float g_h[NN * HH];        // node features
__device__ float g_z[NN * HH];        // pre-MLP features
__device__ int   g_src[EE];
__device__ int   g_dst[EE];
__device__ int   g_csr_src[EE];       // src sorted by dst
__device__ float g_csr_ea[EE];        // edge_attr sorted by dst
__device__ int   g_deg[NN];
__device__ int   g_off[NN + 1];
__device__ int   g_fill[NN];
__device__ int   g_batch[NN];
__device__ float g_pooled[GG * HH];
__device__ float g_cnt[GG];
__device__ float g_hc[GG * 64];
__device__ int   g_flag[2];           // [0]: edge_index is int64, [1]: batch is int64

// ---------------- zero kernel ----------------
__global__ void k_zero() {
    int i = blockIdx.x * blockDim.x + threadIdx.x;
    if (i < NN) { g_deg[i] = 0; g_fill[i] = 0; }
    if (i < GG * HH) g_pooled[i] = 0.0f;
    if (i < GG) g_cnt[i] = 0.0f;
}

// ---------------- dtype probe ----------------
// int32 data read as int64 packs two random indices per word -> high word
// almost surely nonzero somewhere in 512 samples; true int64 stays in-range.
__global__ void k_detect(const void* ei, const void* bt) {
    int lane = threadIdx.x;
    bool bad = false;
    const long long* p = (const long long*)ei;
    for (int k = lane; k < 512; k += 32) {
        long long v = p[(long long)k * 3125];
        if (v < 0 || v >= NN) bad = true;
    }
    unsigned m = __ballot_sync(0xffffffffu, bad);
    if (lane == 0) g_flag[0] = (m == 0) ? 1 : 0;

    bad = false;
    const long long* q = (const long long*)bt;
    for (int k = lane; k < 512; k += 32) {
        long long v = q[(long long)k * 97];
        if (v < 0 || v >= GG) bad = true;
    }
    m = __ballot_sync(0xffffffffu, bad);
    if (lane == 0) g_flag[1] = (m == 0) ? 1 : 0;
}

// ---------------- index normalization + degree count ----------------
__global__ void k_cvt_edges(const void* ei) {
    int e = blockIdx.x * blockDim.x + threadIdx.x;
    if (e >= EE) return;
    int s, d;
    if (g_flag[0]) {
        const long long* p = (const long long*)ei;
        s = (int)p[e]; d = (int)p[EE + e];
    } else {
        const int* p = (const int*)ei;
        s = p[e]; d = p[EE + e];
    }
    g_src[e] = s; g_dst[e] = d;
    atomicAdd(&g_deg[d], 1);
}
__global__ void k_cvt_batch(const void* bt) {
    int i = blockIdx.x * blockDim.x + threadIdx.x;
    if (i >= NN) return;
    if (g_flag[1]) g_batch[i] = (int)((const long long*)bt)[i];
    else           g_batch[i] = ((const int*)bt)[i];
}

// ---------------- single-block exclusive scan of degrees ----------------
__global__ void k_scan() {
    const int C = (NN + 1023) / 1024;
    __shared__ int sm[1024];
    int t = threadIdx.x;
    int b0 = t * C, b1 = min(b0 + C, NN);
    int loc = 0;
    for (int i = b0; i < b1; i++) loc += g_deg[i];
    sm[t] = loc;
    __syncthreads();
    for (int d = 1; d < 1024; d <<= 1) {
        int v = 0;
        if (t >= d) v = sm[t - d];
        __syncthreads();
        sm[t] += v;
        __syncthreads();
    }
    int run = sm[t] - loc;
    for (int i = b0; i < b1; i++) { g_off[i] = run; run += g_deg[i]; }
    if (t == 1023) g_off[NN] = sm[1023];
}

// fill CSR with (src, edge_attr) directly — no eid indirection later
__global__ void k_fill(const float* __restrict__ eattr) {
    int e = blockIdx.x * blockDim.x + threadIdx.x;
    if (e >= EE) return;
    int d = g_dst[e];
    int slot = atomicAdd(&g_fill[d], 1);
    int pos = g_off[d] + slot;
    g_csr_src[pos] = g_src[e];
    g_csr_ea[pos]  = eattr[e];
}

// ---------------- layer-0 aggregation (fused node encoder, rank-1 gather) --
// h_i = x_i*ew + eb ; z = (1+eps)*h_i + sum_j relu(x_j*ew + eb + ea*eew + eeb)
__global__ void k_agg0(const float* __restrict__ x,
                       const float* __restrict__ ew,  const float* __restrict__ eb,
                       const float* __restrict__ eew, const float* __restrict__ eeb,
                       const float* __restrict__ eps) {
    int warp = (blockIdx.x * blockDim.x + threadIdx.x) >> 5;
    int lane = threadIdx.x & 31;
    if (warp >= NN) return;
    float epsv = 1.0f + __ldg(&eps[0]);
    float4 ew4  = ((const float4*)ew)[lane];
    float4 eb4  = ((const float4*)eb)[lane];
    float4 eew4 = ((const float4*)eew)[lane];
    float4 eeb4 = ((const float4*)eeb)[lane];
    float xv = __ldg(&x[warp]);
    float4 acc;
    acc.x = epsv * fmaf(xv, ew4.x, eb4.x);
    acc.y = epsv * fmaf(xv, ew4.y, eb4.y);
    acc.z = epsv * fmaf(xv, ew4.z, eb4.z);
    acc.w = epsv * fmaf(xv, ew4.w, eb4.w);
    int i0 = g_off[warp], i1 = g_off[warp + 1];
    for (int base = i0; base < i1; base += 32) {
        int cnt = min(32, i1 - base);
        float xs = 0.0f, av = 0.0f;
        if (lane < cnt) {
            int s = __ldg(&g_csr_src[base + lane]);
            xs = __ldg(&x[s]);
            av = __ldg(&g_csr_ea[base + lane]);
        }
        for (int j = 0; j < cnt; j++) {
            float bx = __shfl_sync(0xffffffffu, xs, j);
            float ba = __shfl_sync(0xffffffffu, av, j);
            float m;
            m = fmaf(bx, ew4.x, eb4.x) + fmaf(ba, eew4.x, eeb4.x); acc.x += fmaxf(m, 0.0f);
            m = fmaf(bx, ew4.y, eb4.y) + fmaf(ba, eew4.y, eeb4.y); acc.y += fmaxf(m, 0.0f);
            m = fmaf(bx, ew4.z, eb4.z) + fmaf(ba, eew4.z, eeb4.z); acc.z += fmaxf(m, 0.0f);
            m = fmaf(bx, ew4.w, eb4.w) + fmaf(ba, eew4.w, eeb4.w); acc.w += fmaxf(m, 0.0f);
        }
    }
    ((float4*)g_z)[warp * 32 + lane] = acc;
}

// ---------------- layer>=1 aggregation: z = (1+eps)*h + sum relu(h[src]+e) -
__global__ void k_agg(const float* __restrict__ eew, const float* __restrict__ eeb,
                      const float* __restrict__ eps, int l) {
    int warp = (blockIdx.x * blockDim.x + threadIdx.x) >> 5;
    int lane = threadIdx.x & 31;
    if (warp >= NN) return;
    float epsv = 1.0f + __ldg(&eps[l]);
    float4 eew4 = ((const float4*)eew)[lane];
    float4 eeb4 = ((const float4*)eeb)[lane];
    const float4* hf = (const float4*)g_h;
    float4 acc = hf[warp * 32 + lane];
    acc.x *= epsv; acc.y *= epsv; acc.z *= epsv; acc.w *= epsv;
    int i0 = g_off[warp], i1 = g_off[warp + 1];
    for (int base = i0; base < i1; base += 32) {
        int cnt = min(32, i1 - base);
        int s = 0; float av = 0.0f;
        if (lane < cnt) {
            s  = __ldg(&g_csr_src[base + lane]);
            av = __ldg(&g_csr_ea[base + lane]);
        }
        for (int j = 0; j < cnt; j++) {
            int   bs = __shfl_sync(0xffffffffu, s, j);
            float ba = __shfl_sync(0xffffffffu, av, j);
            float4 hv = hf[bs * 32 + lane];
            float m;
            m = hv.x + fmaf(ba, eew4.x, eeb4.x); acc.x += fmaxf(m, 0.0f);
            m = hv.y + fmaf(ba, eew4.y, eeb4.y); acc.y += fmaxf(m, 0.0f);
            m = hv.z + fmaf(ba, eew4.z, eeb4.z); acc.z += fmaxf(m, 0.0f);
            m = hv.w + fmaf(ba, eew4.w, eeb4.w); acc.w += fmaxf(m, 0.0f);
        }
    }
    ((float4*)g_z)[warp * 32 + lane] = acc;
}

// ---------------- fused MLP + BN(eval) + ReLU ----------------
// h = relu(gamma * (relu(z@w1+b1)@w2 + b2) * inv_std + beta)
// 512 threads, TR=128 rows/block, 192 KB smem, 16 warps/SM.
__global__ __launch_bounds__(512, 1)
void k_mlp(const float* __restrict__ w1, const float* __restrict__ b1,
           const float* __restrict__ w2, const float* __restrict__ b2,
           const float* __restrict__ gam, const float* __restrict__ bet) {
    extern __shared__ float sm[];
    float4* sw1 = (float4*)sm;             // 4096 float4 (64KB)
    float4* sw2 = (float4*)(sm + 16384);   // 4096 float4 (64KB)
    float4* st  = (float4*)(sm + 32768);   // TR*32 float4 (64KB)
    int tid = threadIdx.x;

    const float4* w1f = (const float4*)w1;
    const float4* w2f = (const float4*)w2;
    for (int i = tid; i < 4096; i += 512) { sw1[i] = w1f[i]; sw2[i] = w2f[i]; }

    int r0 = blockIdx.x * TR;
    const float4* zf = (const float4*)g_z;
    for (int i = tid; i < TR * 32; i += 512) {
        int r = r0 + (i >> 5);
        st[i] = (r < NN) ? zf[r * 32 + (i & 31)] : make_float4(0.f, 0.f, 0.f, 0.f);
    }
    __syncthreads();

    int c4 = tid & 31;          // owns cols 4*c4 .. 4*c4+3
    int rg = tid >> 5;          // warp id = row group 0..15
    float4 acc[8];
#pragma unroll
    for (int j = 0; j < 8; j++) acc[j] = make_float4(0.f, 0.f, 0.f, 0.f);

    // ---- matmul 1: u = z @ w1 ----
    for (int k = 0; k < 128; k += 4) {
        float4 wa = sw1[(k + 0) * 32 + c4];
        float4 wb = sw1[(k + 1) * 32 + c4];
        float4 wc = sw1[(k + 2) * 32 + c4];
        float4 wd = sw1[(k + 3) * 32 + c4];
#pragma unroll
        for (int j = 0; j < 8; j++) {
            float4 zv = st[(rg + 16 * j) * 32 + (k >> 2)];
            acc[j].x += zv.x * wa.x + zv.y * wb.x + zv.z * wc.x + zv.w * wd.x;
            acc[j].y += zv.x * wa.y + zv.y * wb.y + zv.z * wc.y + zv.w * wd.y;
            acc[j].z += zv.x * wa.z + zv.y * wb.z + zv.z * wc.z + zv.w * wd.z;
            acc[j].w += zv.x * wa.w + zv.y * wb.w + zv.z * wc.w + zv.w * wd.w;
        }
    }
    float4 b1v = ((const float4*)b1)[c4];
    __syncthreads();
#pragma unroll
    for (int j = 0; j < 8; j++) {
        float4 u;
        u.x = fmaxf(acc[j].x + b1v.x, 0.0f);
        u.y = fmaxf(acc[j].y + b1v.y, 0.0f);
        u.z = fmaxf(acc[j].z + b1v.z, 0.0f);
        u.w = fmaxf(acc[j].w + b1v.w, 0.0f);
        st[(rg + 16 * j) * 32 + c4] = u;
        acc[j] = make_float4(0.f, 0.f, 0.f, 0.f);
    }
    __syncthreads();

    // ---- matmul 2: y = u @ w2 ----
    for (int k = 0; k < 128; k += 4) {
        float4 wa = sw2[(k + 0) * 32 + c4];
        float4 wb = sw2[(k + 1) * 32 + c4];
        float4 wc = sw2[(k + 2) * 32 + c4];
        float4 wd = sw2[(k + 3) * 32 + c4];
#pragma unroll
        for (int j = 0; j < 8; j++) {
            float4 uv = st[(rg + 16 * j) * 32 + (k >> 2)];
            acc[j].x += uv.x * wa.x + uv.y * wb.x + uv.z * wc.x + uv.w * wd.x;
            acc[j].y += uv.x * wa.y + uv.y * wb.y + uv.z * wc.y + uv.w * wd.y;
            acc[j].z += uv.x * wa.z + uv.y * wb.z + uv.z * wc.z + uv.w * wd.z;
            acc[j].w += uv.x * wa.w + uv.y * wb.w + uv.z * wc.w + uv.w * wd.w;
        }
    }
    float4 b2v = ((const float4*)b2)[c4];
    float4 gv  = ((const float4*)gam)[c4];
    float4 bv  = ((const float4*)bet)[c4];
#pragma unroll
    for (int j = 0; j < 8; j++) {
        int gr = r0 + rg + 16 * j;
        if (gr < NN) {
            float4 o;
            o.x = fmaxf(gv.x * (acc[j].x + b2v.x) * INV_STD + bv.x, 0.0f);
            o.y = fmaxf(gv.y * (acc[j].y + b2v.y) * INV_STD + bv.y, 0.0f);
            o.z = fmaxf(gv.z * (acc[j].z + b2v.z) * INV_STD + bv.z, 0.0f);
            o.w = fmaxf(gv.w * (acc[j].w + b2v.w) * INV_STD + bv.w, 0.0f);
            ((float4*)g_h)[gr * 32 + c4] = o;
        }
    }
}

// ---------------- mean pool (batch is sorted: accumulate + flush) --------
__global__ void k_pool() {
    int c = threadIdx.x;                 // 128 threads = 128 cols
    int i0 = blockIdx.x * 1024;
    int i1 = min(i0 + 1024, NN);
    if (i0 >= NN) return;
    int gcur = g_batch[i0];
    float acc = 0.0f, cacc = 0.0f;
    for (int i = i0; i < i1; i++) {
        int b = g_batch[i];
        if (b != gcur) {
            atomicAdd(&g_pooled[gcur * HH + c], acc);
            if (c == 0) atomicAdd(&g_cnt[gcur], cacc);
            acc = 0.0f; cacc = 0.0f; gcur = b;
        }
        acc += g_h[i * HH + c];
        cacc += 1.0f;
    }
    atomicAdd(&g_pooled[gcur * HH + c], acc);
    if (c == 0) atomicAdd(&g_cnt[gcur], cacc);
}

// ---------------- classifier ----------------
__global__ void k_cls1(const float* __restrict__ cw1, const float* __restrict__ cb1) {
    int idx = blockIdx.x * blockDim.x + threadIdx.x;   // 4096 = 64 graphs * 64 hid
    if (idx >= GG * 64) return;
    int g = idx >> 6, j = idx & 63;
    float s = 0.0f;
    for (int c = 0; c < HH; c++)
        s = fmaf(g_pooled[g * HH + c], __ldg(&cw1[c * 64 + j]), s);
    float cn = fmaxf(g_cnt[g], 1.0f);
    g_hc[idx] = fmaxf(s / cn + __ldg(&cb1[j]), 0.0f);
}
__global__ void k_cls2(const float* __restrict__ cw2, const float* __restrict__ cb2,
                       float* __restrict__ out) {
    int g = threadIdx.x;
    if (g >= GG) return;
    float s = __ldg(&cb2[0]);
    for (int j = 0; j < 64; j++)
        s = fmaf(g_hc[g * 64 + j], __ldg(&cw2[j]), s);
    out[g] = 1.0f / (1.0f + expf(-s));
}

// ---------------- launch ----------------
extern "C" void kernel_launch(void* const* d_in, const int* in_sizes, int n_in,
                              void* d_out, int out_size) {
    const float* x      = (const float*)d_in[0];
    const void*  ei     = d_in[1];
    const float* eattr  = (const float*)d_in[2];
    const void*  bt     = d_in[3];
    const float* enc_w  = (const float*)d_in[4];
    const float* enc_b  = (const float*)d_in[5];
    const float* eenc_w = (const float*)d_in[6];
    const float* eenc_b = (const float*)d_in[7];
    const float* eps    = (const float*)d_in[8];
    const float* w1     = (const float*)d_in[9];
    const float* b1     = (const float*)d_in[10];
    const float* w2     = (const float*)d_in[11];
    const float* b2     = (const float*)d_in[12];
    const float* gamma  = (const float*)d_in[13];
    const float* beta   = (const float*)d_in[14];
    const float* cw1    = (const float*)d_in[15];
    const float* cb1    = (const float*)d_in[16];
    const float* cw2    = (const float*)d_in[17];
    const float* cb2    = (const float*)d_in[18];
    float* out = (float*)d_out;

    cudaFuncSetAttribute(k_mlp, cudaFuncAttributeMaxDynamicSharedMemorySize, 196608);

    k_zero<<<(NN + 255) / 256, 256>>>();
    k_detect<<<1, 32>>>(ei, bt);
    k_cvt_edges<<<(EE + 255) / 256, 256>>>(ei);
    k_cvt_batch<<<(NN + 255) / 256, 256>>>(bt);
    k_scan<<<1, 1024>>>();
    k_fill<<<(EE + 255) / 256, 256>>>(eattr);

    // layer 0 (fused encoder)
    k_agg0<<<(NN + 7) / 8, 256>>>(x, enc_w, enc_b, eenc_w, eenc_b, eps);
    k_mlp<<<(NN + TR - 1) / TR, 512, 196608>>>(w1, b1, w2, b2, gamma, beta);

    // layer 1
    k_agg<<<(NN + 7) / 8, 256>>>(eenc_w, eenc_b, eps, 1);
    k_mlp<<<(NN + TR - 1) / TR, 512, 196608>>>(
        w1 + HH * HH, b1 + HH, w2 + HH * HH, b2 + HH, gamma + HH, beta + HH);

    k_pool<<<(NN + 1023) / 1024, 128>>>();
    k_cls1<<<(GG * 64 + 255) / 256, 256>>>(cw1, cb1);
    k_cls2<<<1, 64>>>(cw2, cb2, out);
}

// round 4
// speedup vs baseline: 1.1706x; 1.0363x over previous
#include <cuda_runtime.h>
#include <math.h>
#include <stdint.h>

#define NN 100000
#define EE 1600000
#define HH 128
#define GG 64
#define LL 2
#define TR 128          // MLP rows per block
#define INV_STD 0.9999950000374997f

// ---------------- scratch (device globals; no allocation) ----------------
__device__ float g_h[NN * HH];
__device__ float g_z[NN * HH];
__device__ int   g_src[EE];
__device__ int   g_dst[EE];
__device__ int   g_csr_src[EE];
__device__ float g_csr_ea[EE];
__device__ int   g_deg[NN];
__device__ int   g_off[NN + 1];
__device__ int   g_fill[NN];
__device__ int   g_batch[NN];
__device__ float g_pooled[GG * HH];
__device__ float g_cnt[GG];
__device__ float g_hc[GG * 64];
__device__ int   g_flag[2];

// ---------------- zero kernel ----------------
__global__ void k_zero() {
    int i = blockIdx.x * blockDim.x + threadIdx.x;
    if (i < NN) { g_deg[i] = 0; g_fill[i] = 0; }
    if (i < GG * HH) g_pooled[i] = 0.0f;
    if (i < GG) g_cnt[i] = 0.0f;
}

// ---------------- dtype probe ----------------
__global__ void k_detect(const void* ei, const void* bt) {
    int lane = threadIdx.x;
    bool bad = false;
    const long long* p = (const long long*)ei;
    for (int k = lane; k < 512; k += 32) {
        long long v = p[(long long)k * 3125];
        if (v < 0 || v >= NN) bad = true;
    }
    unsigned m = __ballot_sync(0xffffffffu, bad);
    if (lane == 0) g_flag[0] = (m == 0) ? 1 : 0;

    bad = false;
    const long long* q = (const long long*)bt;
    for (int k = lane; k < 512; k += 32) {
        long long v = q[(long long)k * 97];
        if (v < 0 || v >= GG) bad = true;
    }
    m = __ballot_sync(0xffffffffu, bad);
    if (lane == 0) g_flag[1] = (m == 0) ? 1 : 0;
}

// ---------------- index normalization + degree count ----------------
__global__ void k_cvt_edges(const void* ei) {
    int e = blockIdx.x * blockDim.x + threadIdx.x;
    if (e >= EE) return;
    int s, d;
    if (g_flag[0]) {
        const long long* p = (const long long*)ei;
        s = (int)p[e]; d = (int)p[EE + e];
    } else {
        const int* p = (const int*)ei;
        s = p[e]; d = p[EE + e];
    }
    g_src[e] = s; g_dst[e] = d;
    atomicAdd(&g_deg[d], 1);
}
__global__ void k_cvt_batch(const void* bt) {
    int i = blockIdx.x * blockDim.x + threadIdx.x;
    if (i >= NN) return;
    if (g_flag[1]) g_batch[i] = (int)((const long long*)bt)[i];
    else           g_batch[i] = ((const int*)bt)[i];
}

// ---------------- single-block exclusive scan of degrees ----------------
__global__ void k_scan() {
    const int C = (NN + 1023) / 1024;
    __shared__ int sm[1024];
    int t = threadIdx.x;
    int b0 = t * C, b1 = min(b0 + C, NN);
    int loc = 0;
    for (int i = b0; i < b1; i++) loc += g_deg[i];
    sm[t] = loc;
    __syncthreads();
    for (int d = 1; d < 1024; d <<= 1) {
        int v = 0;
        if (t >= d) v = sm[t - d];
        __syncthreads();
        sm[t] += v;
        __syncthreads();
    }
    int run = sm[t] - loc;
    for (int i = b0; i < b1; i++) { g_off[i] = run; run += g_deg[i]; }
    if (t == 1023) g_off[NN] = sm[1023];
}

__global__ void k_fill(const float* __restrict__ eattr) {
    int e = blockIdx.x * blockDim.x + threadIdx.x;
    if (e >= EE) return;
    int d = g_dst[e];
    int slot = atomicAdd(&g_fill[d], 1);
    int pos = g_off[d] + slot;
    g_csr_src[pos] = g_src[e];
    g_csr_ea[pos]  = eattr[e];
}

// ---------------- layer-0 aggregation (fused encoder, rank-1 gather) -----
__global__ void k_agg0(const float* __restrict__ x,
                       const float* __restrict__ ew,  const float* __restrict__ eb,
                       const float* __restrict__ eew, const float* __restrict__ eeb,
                       const float* __restrict__ eps) {
    int warp = (blockIdx.x * blockDim.x + threadIdx.x) >> 5;
    int lane = threadIdx.x & 31;
    if (warp >= NN) return;
    float epsv = 1.0f + __ldg(&eps[0]);
    float4 ew4  = ((const float4*)ew)[lane];
    float4 eb4  = ((const float4*)eb)[lane];
    float4 eew4 = ((const float4*)eew)[lane];
    float4 eeb4 = ((const float4*)eeb)[lane];
    float xv = __ldg(&x[warp]);
    float4 acc;
    acc.x = epsv * fmaf(xv, ew4.x, eb4.x);
    acc.y = epsv * fmaf(xv, ew4.y, eb4.y);
    acc.z = epsv * fmaf(xv, ew4.z, eb4.z);
    acc.w = epsv * fmaf(xv, ew4.w, eb4.w);
    int i0 = g_off[warp], i1 = g_off[warp + 1];
    for (int base = i0; base < i1; base += 32) {
        int cnt = min(32, i1 - base);
        float xs = 0.0f, av = 0.0f;
        if (lane < cnt) {
            int s = __ldg(&g_csr_src[base + lane]);
            xs = __ldg(&x[s]);
            av = __ldg(&g_csr_ea[base + lane]);
        }
        for (int j = 0; j < cnt; j++) {
            float bx = __shfl_sync(0xffffffffu, xs, j);
            float ba = __shfl_sync(0xffffffffu, av, j);
            float m;
            m = fmaf(bx, ew4.x, eb4.x) + fmaf(ba, eew4.x, eeb4.x); acc.x += fmaxf(m, 0.0f);
            m = fmaf(bx, ew4.y, eb4.y) + fmaf(ba, eew4.y, eeb4.y); acc.y += fmaxf(m, 0.0f);
            m = fmaf(bx, ew4.z, eb4.z) + fmaf(ba, eew4.z, eeb4.z); acc.z += fmaxf(m, 0.0f);
            m = fmaf(bx, ew4.w, eb4.w) + fmaf(ba, eew4.w, eeb4.w); acc.w += fmaxf(m, 0.0f);
        }
    }
    ((float4*)g_z)[warp * 32 + lane] = acc;
}

// ---------------- layer>=1 aggregation ----------------
__global__ void k_agg(const float* __restrict__ eew, const float* __restrict__ eeb,
                      const float* __restrict__ eps, int l) {
    int warp = (blockIdx.x * blockDim.x + threadIdx.x) >> 5;
    int lane = threadIdx.x & 31;
    if (warp >= NN) return;
    float epsv = 1.0f + __ldg(&eps[l]);
    float4 eew4 = ((const float4*)eew)[lane];
    float4 eeb4 = ((const float4*)eeb)[lane];
    const float4* hf = (const float4*)g_h;
    float4 acc = hf[warp * 32 + lane];
    acc.x *= epsv; acc.y *= epsv; acc.z *= epsv; acc.w *= epsv;
    int i0 = g_off[warp], i1 = g_off[warp + 1];
    for (int base = i0; base < i1; base += 32) {
        int cnt = min(32, i1 - base);
        int s = 0; float av = 0.0f;
        if (lane < cnt) {
            s  = __ldg(&g_csr_src[base + lane]);
            av = __ldg(&g_csr_ea[base + lane]);
        }
        for (int j = 0; j < cnt; j++) {
            int   bs = __shfl_sync(0xffffffffu, s, j);
            float ba = __shfl_sync(0xffffffffu, av, j);
            float4 hv = hf[bs * 32 + lane];
            float m;
            m = hv.x + fmaf(ba, eew4.x, eeb4.x); acc.x += fmaxf(m, 0.0f);
            m = hv.y + fmaf(ba, eew4.y, eeb4.y); acc.y += fmaxf(m, 0.0f);
            m = hv.z + fmaf(ba, eew4.z, eeb4.z); acc.z += fmaxf(m, 0.0f);
            m = hv.w + fmaf(ba, eew4.w, eeb4.w); acc.w += fmaxf(m, 0.0f);
        }
    }
    ((float4*)g_z)[warp * 32 + lane] = acc;
}

// ================= tensor-core MLP (tf32 mma, 3-pass compensated) =========
// h = relu(gamma * (relu(z@w1+b1)@w2 + b2) * inv_std + beta)
// Layouts:
//  As: A-fragment swizzle, [8 rowtiles][16 ksteps][33 lanes] float4 (padding
//      lane dim 32->33 kills STS bank conflicts; LDS.128 stays conflict-free).
//  Wh/Wl: B-fragment swizzle, [16 ksteps][16 ntiles][32 lanes] uint2 holding
//      tf32 hi / lo bit patterns (conflict-free LDS.64).

__device__ __forceinline__ unsigned f2tf(float x) {
    unsigned r;
    asm("cvt.rna.tf32.f32 %0, %1;" : "=r"(r) : "f"(x));
    return r;
}
__device__ __forceinline__ void mma8(float* c, const unsigned* a, unsigned b0, unsigned b1) {
    asm volatile("mma.sync.aligned.m16n8k8.row.col.f32.tf32.tf32.f32 "
                 "{%0,%1,%2,%3},{%4,%5,%6,%7},{%8,%9},{%0,%1,%2,%3};"
                 : "+f"(c[0]), "+f"(c[1]), "+f"(c[2]), "+f"(c[3])
                 : "r"(a[0]), "r"(a[1]), "r"(a[2]), "r"(a[3]), "r"(b0), "r"(b1));
}
__device__ __forceinline__ void as_store(float* As, int r, int c, float v) {
    int rt = r >> 4, ks = c >> 3;
    int lane = ((r & 7) << 2) + (c & 3);
    int comp = ((r >> 3) & 1) + (((c >> 2) & 1) << 1);
    As[(((rt << 4) + ks) * 33 + lane) * 4 + comp] = v;
}

__device__ __forceinline__ void build_w(uint2* Wh, uint2* Wl,
                                        const float* __restrict__ w, int tid) {
    for (int idx = tid; idx < 16 * 16 * 32; idx += 256) {
        int lane = idx & 31, nt = (idx >> 5) & 15, ks = idx >> 9;
        int k = ks * 8 + (lane & 3);
        int n = nt * 8 + (lane >> 2);
        float w0 = __ldg(&w[k * 128 + n]);
        float w1v = __ldg(&w[(k + 4) * 128 + n]);
        unsigned h0 = f2tf(w0), h1 = f2tf(w1v);
        unsigned l0 = f2tf(w0 - __uint_as_float(h0));
        unsigned l1 = f2tf(w1v - __uint_as_float(h1));
        Wh[idx] = make_uint2(h0, h1);
        Wl[idx] = make_uint2(l0, l1);
    }
}

__device__ __forceinline__ void gemm_frag(const float* As, const uint2* Wh, const uint2* Wl,
                                          int rt, int lane, float C[16][4]) {
    const float4* As4 = (const float4*)As;
#pragma unroll
    for (int ks = 0; ks < 16; ks++) {
        float4 av = As4[(rt * 16 + ks) * 33 + lane];
        unsigned ah[4], al[4];
        ah[0] = f2tf(av.x); al[0] = f2tf(av.x - __uint_as_float(ah[0]));
        ah[1] = f2tf(av.y); al[1] = f2tf(av.y - __uint_as_float(ah[1]));
        ah[2] = f2tf(av.z); al[2] = f2tf(av.z - __uint_as_float(ah[2]));
        ah[3] = f2tf(av.w); al[3] = f2tf(av.w - __uint_as_float(ah[3]));
#pragma unroll
        for (int nt = 0; nt < 16; nt++) {
            uint2 bh = Wh[(ks * 16 + nt) * 32 + lane];
            uint2 bl = Wl[(ks * 16 + nt) * 32 + lane];
            mma8(C[nt], ah, bh.x, bh.y);
            mma8(C[nt], ah, bl.x, bl.y);
            mma8(C[nt], al, bh.x, bh.y);
        }
    }
}

__global__ __launch_bounds__(256, 1)
void k_mlp(const float* __restrict__ w1, const float* __restrict__ b1,
           const float* __restrict__ w2, const float* __restrict__ b2,
           const float* __restrict__ gam, const float* __restrict__ bet) {
    extern __shared__ float smem[];
    float* As = smem;                          // 8*16*33*4 floats = 67584 B
    uint2* Wh = (uint2*)(smem + 16896);        // 65536 B
    uint2* Wl = Wh + 8192;                     // 65536 B
    int tid = threadIdx.x;
    int lane = tid & 31;
    int rt = tid >> 5;                         // warp id 0..7 = row tile
    int p = lane & 3, q = lane >> 2;           // frag coords
    int r0 = blockIdx.x * TR;

    // stage z tile into A-frag layout
    const float4* zf = (const float4*)g_z;
    for (int idx = tid; idx < TR * 32; idx += 256) {
        int r = idx >> 5, c4 = idx & 31;
        int gr = r0 + r;
        float4 zv = (gr < NN) ? zf[gr * 32 + c4] : make_float4(0.f, 0.f, 0.f, 0.f);
        as_store(As, r, c4 * 4 + 0, zv.x);
        as_store(As, r, c4 * 4 + 1, zv.y);
        as_store(As, r, c4 * 4 + 2, zv.z);
        as_store(As, r, c4 * 4 + 3, zv.w);
    }
    build_w(Wh, Wl, w1, tid);
    __syncthreads();

    float C[16][4];
#pragma unroll
    for (int nt = 0; nt < 16; nt++)
#pragma unroll
        for (int i = 0; i < 4; i++) C[nt][i] = 0.0f;

    // ---- GEMM1: u = z @ w1 ----
    gemm_frag(As, Wh, Wl, rt, lane, C);
    __syncthreads();     // all warps done reading Wh/Wl (w1)

    // relu(u + b1) -> back into As (warp-local row range)
#pragma unroll
    for (int nt = 0; nt < 16; nt++) {
        int c0 = nt * 8 + 2 * p;
        float2 b1v = *(const float2*)&b1[c0];
        int rA = rt * 16 + q, rB = rA + 8;
        as_store(As, rA, c0,     fmaxf(C[nt][0] + b1v.x, 0.0f));
        as_store(As, rA, c0 + 1, fmaxf(C[nt][1] + b1v.y, 0.0f));
        as_store(As, rB, c0,     fmaxf(C[nt][2] + b1v.x, 0.0f));
        as_store(As, rB, c0 + 1, fmaxf(C[nt][3] + b1v.y, 0.0f));
#pragma unroll
        for (int i = 0; i < 4; i++) C[nt][i] = 0.0f;
    }
    build_w(Wh, Wl, w2, tid);
    __syncthreads();

    // ---- GEMM2: y = u @ w2 ----
    gemm_frag(As, Wh, Wl, rt, lane, C);

    // epilogue: BN(eval) + ReLU -> g_h
#pragma unroll
    for (int nt = 0; nt < 16; nt++) {
        int c0 = nt * 8 + 2 * p;
        float2 b2v = *(const float2*)&b2[c0];
        float2 gv  = *(const float2*)&gam[c0];
        float2 bv  = *(const float2*)&bet[c0];
        int grA = r0 + rt * 16 + q;
        int grB = grA + 8;
        if (grA < NN) {
            float2 o;
            o.x = fmaxf(gv.x * (C[nt][0] + b2v.x) * INV_STD + bv.x, 0.0f);
            o.y = fmaxf(gv.y * (C[nt][1] + b2v.y) * INV_STD + bv.y, 0.0f);
            *(float2*)&g_h[grA * HH + c0] = o;
        }
        if (grB < NN) {
            float2 o;
            o.x = fmaxf(gv.x * (C[nt][2] + b2v.x) * INV_STD + bv.x, 0.0f);
            o.y = fmaxf(gv.y * (C[nt][3] + b2v.y) * INV_STD + bv.y, 0.0f);
            *(float2*)&g_h[grB * HH + c0] = o;
        }
    }
}

// ---------------- mean pool ----------------
__global__ void k_pool() {
    int c = threadIdx.x;
    int i0 = blockIdx.x * 1024;
    int i1 = min(i0 + 1024, NN);
    if (i0 >= NN) return;
    int gcur = g_batch[i0];
    float acc = 0.0f, cacc = 0.0f;
    for (int i = i0; i < i1; i++) {
        int b = g_batch[i];
        if (b != gcur) {
            atomicAdd(&g_pooled[gcur * HH + c], acc);
            if (c == 0) atomicAdd(&g_cnt[gcur], cacc);
            acc = 0.0f; cacc = 0.0f; gcur = b;
        }
        acc += g_h[i * HH + c];
        cacc += 1.0f;
    }
    atomicAdd(&g_pooled[gcur * HH + c], acc);
    if (c == 0) atomicAdd(&g_cnt[gcur], cacc);
}

// ---------------- classifier ----------------
__global__ void k_cls1(const float* __restrict__ cw1, const float* __restrict__ cb1) {
    int idx = blockIdx.x * blockDim.x + threadIdx.x;
    if (idx >= GG * 64) return;
    int g = idx >> 6, j = idx & 63;
    float s = 0.0f;
    for (int c = 0; c < HH; c++)
        s = fmaf(g_pooled[g * HH + c], __ldg(&cw1[c * 64 + j]), s);
    float cn = fmaxf(g_cnt[g], 1.0f);
    g_hc[idx] = fmaxf(s / cn + __ldg(&cb1[j]), 0.0f);
}
__global__ void k_cls2(const float* __restrict__ cw2, const float* __restrict__ cb2,
                       float* __restrict__ out) {
    int g = threadIdx.x;
    if (g >= GG) return;
    float s = __ldg(&cb2[0]);
    for (int j = 0; j < 64; j++)
        s = fmaf(g_hc[g * 64 + j], __ldg(&cw2[j]), s);
    out[g] = 1.0f / (1.0f + expf(-s));
}

// ---------------- launch ----------------
extern "C" void kernel_launch(void* const* d_in, const int* in_sizes, int n_in,
                              void* d_out, int out_size) {
    const float* x      = (const float*)d_in[0];
    const void*  ei     = d_in[1];
    const float* eattr  = (const float*)d_in[2];
    const void*  bt     = d_in[3];
    const float* enc_w  = (const float*)d_in[4];
    const float* enc_b  = (const float*)d_in[5];
    const float* eenc_w = (const float*)d_in[6];
    const float* eenc_b = (const float*)d_in[7];
    const float* eps    = (const float*)d_in[8];
    const float* w1     = (const float*)d_in[9];
    const float* b1     = (const float*)d_in[10];
    const float* w2     = (const float*)d_in[11];
    const float* b2     = (const float*)d_in[12];
    const float* gamma  = (const float*)d_in[13];
    const float* beta   = (const float*)d_in[14];
    const float* cw1    = (const float*)d_in[15];
    const float* cb1    = (const float*)d_in[16];
    const float* cw2    = (const float*)d_in[17];
    const float* cb2    = (const float*)d_in[18];
    float* out = (float*)d_out;

    cudaFuncSetAttribute(k_mlp, cudaFuncAttributeMaxDynamicSharedMemorySize, 198656);

    k_zero<<<(NN + 255) / 256, 256>>>();
    k_detect<<<1, 32>>>(ei, bt);
    k_cvt_edges<<<(EE + 255) / 256, 256>>>(ei);
    k_cvt_batch<<<(NN + 255) / 256, 256>>>(bt);
    k_scan<<<1, 1024>>>();
    k_fill<<<(EE + 255) / 256, 256>>>(eattr);

    const int MB = (NN + TR - 1) / TR;
    // layer 0 (fused encoder)
    k_agg0<<<(NN + 7) / 8, 256>>>(x, enc_w, enc_b, eenc_w, eenc_b, eps);
    k_mlp<<<MB, 256, 198656>>>(w1, b1, w2, b2, gamma, beta);
    // layer 1
    k_agg<<<(NN + 7) / 8, 256>>>(eenc_w, eenc_b, eps, 1);
    k_mlp<<<MB, 256, 198656>>>(
        w1 + HH * HH, b1 + HH, w2 + HH * HH, b2 + HH, gamma + HH, beta + HH);

    k_pool<<<(NN + 1023) / 1024, 128>>>();
    k_cls1<<<(GG * 64 + 255) / 256, 256>>>(cw1, cb1);
    k_cls2<<<1, 64>>>(cw2, cb2, out);
}